// round 6
// baseline (speedup 1.0000x reference)
#include <cuda_runtime.h>
#include <cuda_bf16.h>
#include <cstdint>

// ---------------------------------------------------------------------------
// GCN, 4 layers, restructured:  h_out = relu( (A @ h) @ W + b )
//   SpMM (pure gather-sum, tf32-rounded output) FIRST, then mma.sync tf32
//   GEMM (pre-rounded W, pure LDS+MMA hot loop) with fused bias+relu.
// Harness builds sm_103 (no 'a') -> tcgen05 unavailable; legacy mma.sync path.
// edge_index arrives as int32 [2, E] (harness downcasts int64).
// ---------------------------------------------------------------------------

#define NMAX     10016
#define EMAX     200032
#define CDIM     512

__device__ float g_buf[2][NMAX * CDIM];   // ping-pong feature buffers
__device__ float g_wr[4][CDIM * CDIM];    // tf32-pre-rounded weights
__device__ int   g_src[EMAX];
__device__ float g_w[EMAX];
__device__ int   g_ptr[NMAX + 1];
__device__ int   g_deg[NMAX];
__device__ int   g_cur[NMAX];
__device__ float g_dinv[NMAX];

__device__ __forceinline__ int clampi(int v, int n) {
    return v < 0 ? 0 : (v >= n ? n - 1 : v);
}

__device__ __forceinline__ uint32_t smem_u32(const void* p) {
    uint32_t a;
    asm("{ .reg .u64 t; cvta.to.shared.u64 t, %1; cvt.u32.u64 %0, t; }"
        : "=r"(a) : "l"(p));
    return a;
}

__device__ __forceinline__ float to_tf32(float x) {
    unsigned u;
    asm("cvt.rna.tf32.f32 %0, %1;" : "=r"(u) : "f"(x));
    return __uint_as_float(u);
}

#define CP_ASYNC16(dst, src) \
    asm volatile("cp.async.cg.shared.global [%0], [%1], 16;" \
                 :: "r"(dst), "l"(src) : "memory")
#define CP_COMMIT()  asm volatile("cp.async.commit_group;" ::: "memory")
#define CP_WAIT2()   asm volatile("cp.async.wait_group 2;" ::: "memory")
#define CP_WAIT1()   asm volatile("cp.async.wait_group 1;" ::: "memory")
#define CP_WAIT0()   asm volatile("cp.async.wait_group 0;" ::: "memory")

// ---------------------------- preprocessing --------------------------------

__global__ void init_kernel(int n) {
    int i = blockIdx.x * blockDim.x + threadIdx.x;
    if (i < n) { g_deg[i] = 1; g_cur[i] = 0; }
}

__global__ void count_kernel(const int* __restrict__ ei, int E, int n) {
    int e = blockIdx.x * blockDim.x + threadIdx.x;
    if (e < E) atomicAdd(&g_deg[clampi(ei[E + e], n)], 1);
}

__global__ void scan_dinv_kernel(int n) {
    __shared__ int warp_tot[32];
    int tid  = threadIdx.x;
    int lane = tid & 31, wid = tid >> 5;
    int per  = (n + 1023) >> 10;
    int beg  = tid * per;
    int end  = min(beg + per, n);

    int local[12];
    int t = 0;
    for (int i = beg; i < end; i++) {
        int d = g_deg[i];
        local[i - beg] = t;
        t += d;
        g_dinv[i] = rsqrtf((float)d);
    }
    int x = t;
    #pragma unroll
    for (int off = 1; off < 32; off <<= 1) {
        int y = __shfl_up_sync(0xffffffffu, x, off);
        if (lane >= off) x += y;
    }
    if (lane == 31) warp_tot[wid] = x;
    __syncthreads();
    if (wid == 0) {
        int v = warp_tot[lane];
        #pragma unroll
        for (int off = 1; off < 32; off <<= 1) {
            int y = __shfl_up_sync(0xffffffffu, v, off);
            if (lane >= off) v += y;
        }
        warp_tot[lane] = v;
    }
    __syncthreads();
    int warp_off = (wid > 0) ? warp_tot[wid - 1] : 0;
    int excl = warp_off + x - t;
    for (int i = beg; i < end; i++) g_ptr[i] = excl + local[i - beg];
    if (tid == 0) g_ptr[n] = warp_tot[31];
}

__global__ void fill_kernel(const int* __restrict__ ei, int E, int n) {
    int e = blockIdx.x * blockDim.x + threadIdx.x;
    if (e >= E + n) return;
    int r, c;
    if (e < E) { r = clampi(ei[e], n); c = clampi(ei[E + e], n); }
    else       { r = c = e - E; }
    int pos = g_ptr[c] + atomicAdd(&g_cur[c], 1);
    if (pos < EMAX) {
        g_src[pos] = r;
        g_w[pos]   = g_dinv[r] * g_dinv[c];
    }
}

// pre-round all 4 weight matrices to tf32 (one launch)
__global__ void wround_kernel(const float* __restrict__ W1,
                              const float* __restrict__ W2,
                              const float* __restrict__ W3,
                              const float* __restrict__ W4, int n1) {
    int i = blockIdx.x * blockDim.x + threadIdx.x;
    if (i < CDIM * CDIM) {
        g_wr[1][i] = to_tf32(W2[i]);
        g_wr[2][i] = to_tf32(W3[i]);
        g_wr[3][i] = to_tf32(W4[i]);
        if (i < n1) g_wr[0][i] = to_tf32(W1[i]);
    }
}

// ------------------------------- CSR SpMM ----------------------------------
// pure aggregation, tf32-rounded output (feeds GEMM A operand only).
__global__ void spmm_agg(const float* __restrict__ xin, int srcsel, int dstsel, int c4)
{
    int v = blockIdx.x;
    int t = threadIdx.x;
    const float4* S = (srcsel < 0) ? (const float4*)xin : (const float4*)g_buf[srcsel];
    float4* D = (float4*)g_buf[dstsel];

    int beg = g_ptr[v], end = g_ptr[v + 1];
    float4 acc = make_float4(0.f, 0.f, 0.f, 0.f);

    int e = beg;
    for (; e + 3 < end; e += 4) {
        int   s0 = g_src[e],     s1 = g_src[e + 1];
        int   s2 = g_src[e + 2], s3 = g_src[e + 3];
        float w0 = g_w[e],       w1 = g_w[e + 1];
        float w2 = g_w[e + 2],   w3 = g_w[e + 3];
        float4 h0 = S[s0 * c4 + t];
        float4 h1 = S[s1 * c4 + t];
        float4 h2 = S[s2 * c4 + t];
        float4 h3 = S[s3 * c4 + t];
        acc.x += w0 * h0.x + w1 * h1.x + w2 * h2.x + w3 * h3.x;
        acc.y += w0 * h0.y + w1 * h1.y + w2 * h2.y + w3 * h3.y;
        acc.z += w0 * h0.z + w1 * h1.z + w2 * h2.z + w3 * h3.z;
        acc.w += w0 * h0.w + w1 * h1.w + w2 * h2.w + w3 * h3.w;
    }
    for (; e < end; e++) {
        int s0 = g_src[e];
        float w0 = g_w[e];
        float4 h0 = S[s0 * c4 + t];
        acc.x += w0 * h0.x; acc.y += w0 * h0.y;
        acc.z += w0 * h0.z; acc.w += w0 * h0.w;
    }
    acc.x = to_tf32(acc.x); acc.y = to_tf32(acc.y);
    acc.z = to_tf32(acc.z); acc.w = to_tf32(acc.w);
    D[v * c4 + t] = acc;
}

// ----------------------- tf32 GEMM (cp.async pipeline) ---------------------
// C[M x 512] = A[M x K] @ W[K x 512] (+bias, +relu); A and W pre-rounded tf32.
// Block 64x128, BK=16, 128 threads (4 warps 2x2), warp tile 32x64.
// 4-stage cp.async.cg pipeline (dynamic smem, occ 4). Hot loop = LDS + MMA.

__device__ __forceinline__ void mma_tf32(float* c, const float* a, const float* b) {
    asm volatile(
        "mma.sync.aligned.m16n8k8.row.col.f32.tf32.tf32.f32 "
        "{%0,%1,%2,%3}, {%4,%5,%6,%7}, {%8,%9}, {%0,%1,%2,%3};"
        : "+f"(c[0]), "+f"(c[1]), "+f"(c[2]), "+f"(c[3])
        : "r"(__float_as_uint(a[0])), "r"(__float_as_uint(a[1])),
          "r"(__float_as_uint(a[2])), "r"(__float_as_uint(a[3])),
          "r"(__float_as_uint(b[0])), "r"(__float_as_uint(b[1])));
}

#define APAD 20         // As row stride
#define BPAD 132        // Bs row stride
#define ABYTES (64 * APAD * 4)          // 5120 per stage
#define BBYTES (16 * BPAD * 4)          // 8448 per stage
#define GDSMEM (4 * (ABYTES + BBYTES))  // 54272

__global__ __launch_bounds__(128)
void gemm_tc(const float* __restrict__ Wt, const float* __restrict__ bias,
             float* __restrict__ dout, int M, int K, int insel, int outsel,
             int relu)
{
    extern __shared__ __align__(16) float dsm[];
    // stage s: As at s*ABYTES, Bs at 4*ABYTES + s*BBYTES (byte offsets)
    const float* A = g_buf[insel];
    float* C = (outsel < 0) ? dout : g_buf[outsel];

    int tid  = threadIdx.x;
    int bm   = blockIdx.x * 64;
    int bn   = blockIdx.y * 128;
    int wid  = tid >> 5, lane = tid & 31;
    int wm   = (wid >> 1) * 32;
    int wn   = (wid & 1) * 64;
    int tg   = lane & 3, gp = lane >> 2;

    float acc[2][8][4];
    #pragma unroll
    for (int mt = 0; mt < 2; mt++)
        #pragma unroll
        for (int nt = 0; nt < 8; nt++)
            #pragma unroll
            for (int q = 0; q < 4; q++) acc[mt][nt][q] = 0.f;

    // A copy map: rows (tid>>2), (tid>>2)+32; k-cols (tid&3)*4
    int a_row = tid >> 2, a_c = (tid & 3) * 4;
    int gr0 = bm + a_row;      if (gr0 >= M) gr0 = M - 1;
    int gr1 = bm + a_row + 32; if (gr1 >= M) gr1 = M - 1;
    // B copy map: k-rows (tid>>5)+{0,4,8,12}; n-cols (tid&31)*4
    int b_r = tid >> 5, b_c = (tid & 31) * 4;

    uint32_t smbase = smem_u32(dsm);
    uint32_t sa0[4], sa1[4], sb[4][4];
    #pragma unroll
    for (int s = 0; s < 4; s++) {
        sa0[s] = smbase + s * ABYTES + (a_row * APAD + a_c) * 4;
        sa1[s] = smbase + s * ABYTES + ((a_row + 32) * APAD + a_c) * 4;
        #pragma unroll
        for (int i = 0; i < 4; i++)
            sb[s][i] = smbase + 4 * ABYTES + s * BBYTES + ((b_r + i * 4) * BPAD + b_c) * 4;
    }

    int ktiles = K >> 4;

    auto prefetch = [&](int kt) {
        int s  = kt & 3;
        int k0 = kt << 4;
        CP_ASYNC16(sa0[s], &A[(size_t)gr0 * K + k0 + a_c]);
        CP_ASYNC16(sa1[s], &A[(size_t)gr1 * K + k0 + a_c]);
        #pragma unroll
        for (int i = 0; i < 4; i++)
            CP_ASYNC16(sb[s][i], &Wt[(size_t)(k0 + b_r + i * 4) * CDIM + bn + b_c]);
        CP_COMMIT();
    };

    prefetch(0);
    prefetch(1);
    prefetch(2);

    for (int kt = 0; kt < ktiles; kt++) {
        if (kt + 3 < ktiles + 2) {
            if (kt + 1 >= ktiles)      CP_WAIT0();
            else if (kt + 2 >= ktiles) CP_WAIT1();
            else                       CP_WAIT2();
        }
        __syncthreads();

        int buf = kt & 3;
        const float* As = dsm + buf * (ABYTES / 4);
        const float* Bs = dsm + ABYTES + buf * (BBYTES / 4);   // 4*ABYTES/4

        #pragma unroll
        for (int kk = 0; kk < 16; kk += 8) {
            float a[2][4], b[8][2];
            #pragma unroll
            for (int mt = 0; mt < 2; mt++) {
                int r = wm + mt * 16 + gp;
                a[mt][0] = As[r * APAD + kk + tg];
                a[mt][1] = As[(r + 8) * APAD + kk + tg];
                a[mt][2] = As[r * APAD + kk + tg + 4];
                a[mt][3] = As[(r + 8) * APAD + kk + tg + 4];
            }
            #pragma unroll
            for (int nt = 0; nt < 8; nt++) {
                int c = wn + nt * 8 + gp;
                b[nt][0] = Bs[(kk + tg) * BPAD + c];
                b[nt][1] = Bs[(kk + tg + 4) * BPAD + c];
            }
            #pragma unroll
            for (int mt = 0; mt < 2; mt++)
                #pragma unroll
                for (int nt = 0; nt < 8; nt++)
                    mma_tf32(acc[mt][nt], a[mt], b[nt]);
        }

        if (kt + 3 < ktiles) prefetch(kt + 3);
    }

    // epilogue: + bias, optional relu
    #pragma unroll
    for (int mt = 0; mt < 2; mt++) {
        #pragma unroll
        for (int nt = 0; nt < 8; nt++) {
            int r = bm + wm + mt * 16 + gp;
            int c = bn + wn + nt * 8 + tg * 2;
            float bb0 = __ldg(&bias[c]), bb1 = __ldg(&bias[c + 1]);
            float v0 = acc[mt][nt][0] + bb0, v1 = acc[mt][nt][1] + bb1;
            float v2 = acc[mt][nt][2] + bb0, v3 = acc[mt][nt][3] + bb1;
            if (relu) {
                v0 = fmaxf(v0, 0.f); v1 = fmaxf(v1, 0.f);
                v2 = fmaxf(v2, 0.f); v3 = fmaxf(v3, 0.f);
            }
            if (r < M)     *(float2*)&C[(size_t)r * CDIM + c]       = make_float2(v0, v1);
            if (r + 8 < M) *(float2*)&C[(size_t)(r + 8) * CDIM + c] = make_float2(v2, v3);
        }
    }
}

// pointer-fetch trampoline for __device__ array bases (host can't take address)
// -> instead pass selector ints as before; weights via g_wr selector:
__global__ void dummy() {}

// ------------------------------- driver ------------------------------------

extern "C" void kernel_launch(void* const* d_in, const int* in_sizes, int n_in,
                              void* d_out, int out_size)
{
    const float* x  = (const float*)d_in[0];
    const int*   ei = (const int*)d_in[1];      // int64 downcast to int32
    const float* W1 = (const float*)d_in[2];
    const float* b1 = (const float*)d_in[3];
    const float* W2 = (const float*)d_in[4];
    const float* b2 = (const float*)d_in[5];
    const float* W3 = (const float*)d_in[6];
    const float* b3 = (const float*)d_in[7];
    const float* W4 = (const float*)d_in[8];
    const float* b4 = (const float*)d_in[9];
    float* out = (float*)d_out;

    int Cin = in_sizes[2] / CDIM;         // 256
    int N   = in_sizes[0] / Cin;          // 10000
    int E   = in_sizes[1] / 2;            // 160000

    static float* wr_host[4] = {nullptr, nullptr, nullptr, nullptr};
    if (!wr_host[0]) {
        void* p;
        cudaGetSymbolAddress(&p, g_wr);
        for (int l = 0; l < 4; l++)
            wr_host[l] = (float*)p + (size_t)l * CDIM * CDIM;
        cudaFuncSetAttribute(gemm_tc, cudaFuncAttributeMaxDynamicSharedMemorySize,
                             GDSMEM);
    }

    // preprocessing
    wround_kernel<<<(CDIM * CDIM + 255) / 256, 256>>>(W1, W2, W3, W4, Cin * CDIM);
    init_kernel<<<(N + 255) / 256, 256>>>(N);
    count_kernel<<<(E + 255) / 256, 256>>>(ei, E, N);
    scan_dinv_kernel<<<1, 1024>>>(N);
    fill_kernel<<<(E + N + 255) / 256, 256>>>(ei, E, N);

    dim3 ggrid((N + 63) / 64, CDIM / 128);   // (157, 4)

    // layer 1: aggregate x (256 cols) -> buf1 ; gemm K=256 (+b1, relu) -> buf0
    spmm_agg<<<N, 64>>>(x, -1, 1, 64);
    gemm_tc<<<ggrid, 128, GDSMEM>>>(wr_host[0], b1, nullptr, N, Cin, 1, 0, 1);
    // layer 2
    spmm_agg<<<N, 128>>>(nullptr, 0, 1, 128);
    gemm_tc<<<ggrid, 128, GDSMEM>>>(wr_host[1], b2, nullptr, N, CDIM, 1, 0, 1);
    // layer 3
    spmm_agg<<<N, 128>>>(nullptr, 0, 1, 128);
    gemm_tc<<<ggrid, 128, GDSMEM>>>(wr_host[2], b3, nullptr, N, CDIM, 1, 0, 1);
    // layer 4 (no relu, write d_out)
    spmm_agg<<<N, 128>>>(nullptr, 0, 1, 128);
    gemm_tc<<<ggrid, 128, GDSMEM>>>(wr_host[3], b4, out, N, CDIM, 1, -1, 0);
}

// round 7
// speedup vs baseline: 1.2454x; 1.2454x over previous
#include <cuda_runtime.h>
#include <cuda_bf16.h>
#include <cstdint>

// ---------------------------------------------------------------------------
// GCN, 4 layers:  h_out = relu( (A @ h) @ W + b )   (SpMM first, then GEMM)
// GEMM: mma.sync m16n8k8 tf32, 64x128 block tile, 4 warps, 3-stage cp.async.
// W pre-rounded to tf32 AND pre-permuted into MMA-fragment order so the GEMM
// B operand loads are LDS.128 (1 per 4 fragments) instead of scalar LDS.
// edge_index arrives as int32 [2, E] (harness downcasts int64).
// ---------------------------------------------------------------------------

#define NMAX     10016
#define EMAX     200032
#define CDIM     512

__device__ float g_buf[2][NMAX * CDIM];   // ping-pong feature buffers
__device__ float g_wr[4][CDIM * CDIM];    // tf32-rounded, fragment-permuted W
__device__ int   g_src[EMAX];
__device__ float g_w[EMAX];
__device__ int   g_ptr[NMAX + 1];
__device__ int   g_deg[NMAX];
__device__ int   g_cur[NMAX];
__device__ float g_dinv[NMAX];

__device__ __forceinline__ int clampi(int v, int n) {
    return v < 0 ? 0 : (v >= n ? n - 1 : v);
}

__device__ __forceinline__ uint32_t smem_u32(const void* p) {
    uint32_t a;
    asm("{ .reg .u64 t; cvta.to.shared.u64 t, %1; cvt.u32.u64 %0, t; }"
        : "=r"(a) : "l"(p));
    return a;
}

__device__ __forceinline__ float to_tf32(float x) {
    unsigned u;
    asm("cvt.rna.tf32.f32 %0, %1;" : "=r"(u) : "f"(x));
    return __uint_as_float(u);
}

#define CP_ASYNC16(dst, src) \
    asm volatile("cp.async.cg.shared.global [%0], [%1], 16;" \
                 :: "r"(dst), "l"(src) : "memory")
#define CP_COMMIT()  asm volatile("cp.async.commit_group;" ::: "memory")
#define CP_WAIT1()   asm volatile("cp.async.wait_group 1;" ::: "memory")
#define CP_WAIT0()   asm volatile("cp.async.wait_group 0;" ::: "memory")

// ---------------------------- preprocessing --------------------------------

__global__ void init_kernel(int n) {
    int i = blockIdx.x * blockDim.x + threadIdx.x;
    if (i < n) { g_deg[i] = 1; g_cur[i] = 0; }
}

__global__ void count_kernel(const int* __restrict__ ei, int E, int n) {
    int e = blockIdx.x * blockDim.x + threadIdx.x;
    if (e < E) atomicAdd(&g_deg[clampi(ei[E + e], n)], 1);
}

// exclusive scan g_deg -> g_ptr + dinv; no local-memory arrays (recompute pass)
__global__ void scan_dinv_kernel(int n) {
    __shared__ int warp_tot[32];
    int tid  = threadIdx.x;
    int lane = tid & 31, wid = tid >> 5;
    int per  = (n + 1023) >> 10;
    int beg  = tid * per;
    int end  = min(beg + per, n);

    int t = 0;
    for (int i = beg; i < end; i++) {
        int d = g_deg[i];
        t += d;
        g_dinv[i] = rsqrtf((float)d);
    }
    int x = t;
    #pragma unroll
    for (int off = 1; off < 32; off <<= 1) {
        int y = __shfl_up_sync(0xffffffffu, x, off);
        if (lane >= off) x += y;
    }
    if (lane == 31) warp_tot[wid] = x;
    __syncthreads();
    if (wid == 0) {
        int v = warp_tot[lane];
        #pragma unroll
        for (int off = 1; off < 32; off <<= 1) {
            int y = __shfl_up_sync(0xffffffffu, v, off);
            if (lane >= off) v += y;
        }
        warp_tot[lane] = v;
    }
    __syncthreads();
    int warp_off = (wid > 0) ? warp_tot[wid - 1] : 0;
    int run = warp_off + x - t;                 // exclusive prefix
    for (int i = beg; i < end; i++) {           // second pass: L1-hot reloads
        g_ptr[i] = run;
        run += g_deg[i];
    }
    if (tid == 0) g_ptr[n] = warp_tot[31];
}

__global__ void fill_kernel(const int* __restrict__ ei, int E, int n) {
    int e = blockIdx.x * blockDim.x + threadIdx.x;
    if (e >= E + n) return;
    int r, c;
    if (e < E) { r = clampi(ei[e], n); c = clampi(ei[E + e], n); }
    else       { r = c = e - E; }
    int pos = g_ptr[c] + atomicAdd(&g_cur[c], 1);
    if (pos < EMAX) {
        g_src[pos] = r;
        g_w[pos]   = g_dinv[r] * g_dinv[c];
    }
}

// ---- weight preprocessing: tf32 round + MMA-fragment permutation ----------
// dst layout, linear index o:
//   e(2b) | lane(5b) | chunk(2b) | wn2(1b) | kk2(1b) | kt(ktshift b) | nb
// value = tf32( W[k, n] ) with
//   tg = lane&3, gp = lane>>5? no: lane>>2
//   nt = chunk*2 + (e>>1), j = e&1
//   k  = kt*16 + kk2*8 + tg + 4*j
//   n  = nb*128 + wn2*64 + nt*8 + gp
__device__ __forceinline__ void permW(float* dst, const float* __restrict__ W,
                                      int o, int ktshift) {
    int e    = o & 3;
    int lane = (o >> 2) & 31;
    int chunk= (o >> 7) & 3;
    int wn2  = (o >> 9) & 1;
    int kk2  = (o >> 10) & 1;
    int rest = o >> 11;
    int kt   = rest & ((1 << ktshift) - 1);
    int nb   = rest >> ktshift;
    int tg = lane & 3, gp = lane >> 2;
    int nt = chunk * 2 + (e >> 1), j = e & 1;
    int k  = kt * 16 + kk2 * 8 + tg + 4 * j;
    int n  = nb * 128 + wn2 * 64 + nt * 8 + gp;
    dst[o] = to_tf32(W[k * CDIM + n]);
}

__global__ void wround_kernel(const float* __restrict__ W1,
                              const float* __restrict__ W2,
                              const float* __restrict__ W3,
                              const float* __restrict__ W4, int n1) {
    int o = blockIdx.x * blockDim.x + threadIdx.x;
    if (o < CDIM * CDIM) {
        permW(g_wr[1], W2, o, 5);
        permW(g_wr[2], W3, o, 5);
        permW(g_wr[3], W4, o, 5);
        if (o < n1) permW(g_wr[0], W1, o, 4);   // K=256 -> KT=16
    }
}

// ------------------------------- CSR SpMM ----------------------------------
// pure aggregation, tf32-rounded output (feeds GEMM A operand only).
__global__ void spmm_agg(const float* __restrict__ xin, int srcsel, int dstsel, int c4)
{
    int v = blockIdx.x;
    int t = threadIdx.x;
    const float4* S = (srcsel < 0) ? (const float4*)xin : (const float4*)g_buf[srcsel];
    float4* D = (float4*)g_buf[dstsel];

    int beg = g_ptr[v], end = g_ptr[v + 1];
    float4 acc = make_float4(0.f, 0.f, 0.f, 0.f);

    int e = beg;
    for (; e + 3 < end; e += 4) {
        int   s0 = g_src[e],     s1 = g_src[e + 1];
        int   s2 = g_src[e + 2], s3 = g_src[e + 3];
        float w0 = g_w[e],       w1 = g_w[e + 1];
        float w2 = g_w[e + 2],   w3 = g_w[e + 3];
        float4 h0 = S[s0 * c4 + t];
        float4 h1 = S[s1 * c4 + t];
        float4 h2 = S[s2 * c4 + t];
        float4 h3 = S[s3 * c4 + t];
        acc.x += w0 * h0.x + w1 * h1.x + w2 * h2.x + w3 * h3.x;
        acc.y += w0 * h0.y + w1 * h1.y + w2 * h2.y + w3 * h3.y;
        acc.z += w0 * h0.z + w1 * h1.z + w2 * h2.z + w3 * h3.z;
        acc.w += w0 * h0.w + w1 * h1.w + w2 * h2.w + w3 * h3.w;
    }
    for (; e < end; e++) {
        int s0 = g_src[e];
        float w0 = g_w[e];
        float4 h0 = S[s0 * c4 + t];
        acc.x += w0 * h0.x; acc.y += w0 * h0.y;
        acc.z += w0 * h0.z; acc.w += w0 * h0.w;
    }
    acc.x = to_tf32(acc.x); acc.y = to_tf32(acc.y);
    acc.z = to_tf32(acc.z); acc.w = to_tf32(acc.w);
    D[v * c4 + t] = acc;
}

// ----------------------- tf32 GEMM (cp.async pipeline) ---------------------
// C[M x 512] = A[M x K] @ W[K x 512] (+bias, +relu); W fragment-permuted.
// Block 64x128, BK=16, 128 threads (4 warps 2x2), warp tile 32x64.
// 3-stage static-smem cp.async pipeline (occ 5). B loads = LDS.128.

__device__ __forceinline__ void mma_tf32(float* c, const float* a, const float* b) {
    asm volatile(
        "mma.sync.aligned.m16n8k8.row.col.f32.tf32.tf32.f32 "
        "{%0,%1,%2,%3}, {%4,%5,%6,%7}, {%8,%9}, {%0,%1,%2,%3};"
        : "+f"(c[0]), "+f"(c[1]), "+f"(c[2]), "+f"(c[3])
        : "r"(__float_as_uint(a[0])), "r"(__float_as_uint(a[1])),
          "r"(__float_as_uint(a[2])), "r"(__float_as_uint(a[3])),
          "r"(__float_as_uint(b[0])), "r"(__float_as_uint(b[1])));
}

#define APAD 20    // As row stride

__global__ __launch_bounds__(128)
void gemm_tc(const float* __restrict__ Wt, const float* __restrict__ bias,
             float* __restrict__ dout, int M, int K, int insel, int outsel,
             int relu)
{
    __shared__ __align__(16) float As[3][64][APAD];   // 15360 B
    __shared__ __align__(16) float Bs[3][2048];       // 24576 B (frag order)

    const float* A = g_buf[insel];
    float* C = (outsel < 0) ? dout : g_buf[outsel];

    int tid  = threadIdx.x;
    int bm   = blockIdx.x * 64;
    int nb   = blockIdx.y;              // n-block of 128
    int bn   = nb * 128;
    int wid  = tid >> 5, lane = tid & 31;
    int wm   = (wid >> 1) * 32;
    int wn   = (wid & 1) * 64;
    int wn2  = wid & 1;
    int tg   = lane & 3, gp = lane >> 2;

    float acc[2][8][4];
    #pragma unroll
    for (int mt = 0; mt < 2; mt++)
        #pragma unroll
        for (int nt = 0; nt < 8; nt++)
            #pragma unroll
            for (int q = 0; q < 4; q++) acc[mt][nt][q] = 0.f;

    // A copy map: rows (tid>>2), (tid>>2)+32; k-cols (tid&3)*4
    int a_row = tid >> 2, a_c = (tid & 3) * 4;
    int gr0 = bm + a_row;      if (gr0 >= M) gr0 = M - 1;
    int gr1 = bm + a_row + 32; if (gr1 >= M) gr1 = M - 1;

    uint32_t sa0[3], sa1[3], sbB[3];
    #pragma unroll
    for (int s = 0; s < 3; s++) {
        sa0[s] = smem_u32(&As[s][a_row][a_c]);
        sa1[s] = smem_u32(&As[s][a_row + 32][a_c]);
        sbB[s] = smem_u32(&Bs[s][0]) + tid * 16;
    }

    int ktiles = K >> 4;

    auto prefetch = [&](int kt) {
        int s  = kt % 3;
        int k0 = kt << 4;
        CP_ASYNC16(sa0[s], &A[(size_t)gr0 * K + k0 + a_c]);
        CP_ASYNC16(sa1[s], &A[(size_t)gr1 * K + k0 + a_c]);
        const float* src = Wt + ((size_t)(nb * ktiles + kt) << 11) + (tid << 2);
        #pragma unroll
        for (int i = 0; i < 4; i++)
            CP_ASYNC16(sbB[s] + i * 2048, src + i * 512);
        CP_COMMIT();
    };

    prefetch(0);
    if (ktiles > 1) prefetch(1); else CP_COMMIT();

    for (int kt = 0; kt < ktiles; kt++) {
        if (kt + 1 < ktiles) CP_WAIT1(); else CP_WAIT0();
        __syncthreads();

        int buf = kt % 3;
        const float (*Asb)[APAD] = As[buf];
        const float4* Bq = (const float4*)&Bs[buf][0];

        #pragma unroll
        for (int kk2 = 0; kk2 < 2; kk2++) {
            int kk = kk2 * 8;
            float a[2][4];
            #pragma unroll
            for (int mt = 0; mt < 2; mt++) {
                int r = wm + mt * 16 + gp;
                a[mt][0] = Asb[r    ][kk + tg];
                a[mt][1] = Asb[r + 8][kk + tg];
                a[mt][2] = Asb[r    ][kk + tg + 4];
                a[mt][3] = Asb[r + 8][kk + tg + 4];
            }
            // fragment-ordered B: 4x LDS.128 per lane
            const float4* bp = Bq + kk2 * 256 + wn2 * 128 + lane;
            float4 bv0 = bp[0], bv1 = bp[32], bv2 = bp[64], bv3 = bp[96];
            float b[8][2] = {
                {bv0.x, bv0.y}, {bv0.z, bv0.w},
                {bv1.x, bv1.y}, {bv1.z, bv1.w},
                {bv2.x, bv2.y}, {bv2.z, bv2.w},
                {bv3.x, bv3.y}, {bv3.z, bv3.w}
            };
            #pragma unroll
            for (int mt = 0; mt < 2; mt++)
                #pragma unroll
                for (int nt = 0; nt < 8; nt++)
                    mma_tf32(acc[mt][nt], a[mt], b[nt]);
        }

        if (kt + 2 < ktiles) prefetch(kt + 2);
    }

    // epilogue: + bias, optional relu
    #pragma unroll
    for (int mt = 0; mt < 2; mt++) {
        #pragma unroll
        for (int nt = 0; nt < 8; nt++) {
            int r = bm + wm + mt * 16 + gp;
            int c = bn + wn + nt * 8 + tg * 2;
            float bb0 = __ldg(&bias[c]), bb1 = __ldg(&bias[c + 1]);
            float v0 = acc[mt][nt][0] + bb0, v1 = acc[mt][nt][1] + bb1;
            float v2 = acc[mt][nt][2] + bb0, v3 = acc[mt][nt][3] + bb1;
            if (relu) {
                v0 = fmaxf(v0, 0.f); v1 = fmaxf(v1, 0.f);
                v2 = fmaxf(v2, 0.f); v3 = fmaxf(v3, 0.f);
            }
            if (r < M)     *(float2*)&C[(size_t)r * CDIM + c]       = make_float2(v0, v1);
            if (r + 8 < M) *(float2*)&C[(size_t)(r + 8) * CDIM + c] = make_float2(v2, v3);
        }
    }
}

// ------------------------------- driver ------------------------------------

extern "C" void kernel_launch(void* const* d_in, const int* in_sizes, int n_in,
                              void* d_out, int out_size)
{
    const float* x  = (const float*)d_in[0];
    const int*   ei = (const int*)d_in[1];      // int64 downcast to int32
    const float* W1 = (const float*)d_in[2];
    const float* b1 = (const float*)d_in[3];
    const float* W2 = (const float*)d_in[4];
    const float* b2 = (const float*)d_in[5];
    const float* W3 = (const float*)d_in[6];
    const float* b3 = (const float*)d_in[7];
    const float* W4 = (const float*)d_in[8];
    const float* b4 = (const float*)d_in[9];
    float* out = (float*)d_out;

    int Cin = in_sizes[2] / CDIM;         // 256
    int N   = in_sizes[0] / Cin;          // 10000
    int E   = in_sizes[1] / 2;            // 160000

    static float* wr_host[4] = {nullptr, nullptr, nullptr, nullptr};
    if (!wr_host[0]) {
        void* p;
        cudaGetSymbolAddress(&p, g_wr);
        for (int l = 0; l < 4; l++)
            wr_host[l] = (float*)p + (size_t)l * CDIM * CDIM;
    }

    // preprocessing
    wround_kernel<<<(CDIM * CDIM + 255) / 256, 256>>>(W1, W2, W3, W4, Cin * CDIM);
    init_kernel<<<(N + 255) / 256, 256>>>(N);
    count_kernel<<<(E + 255) / 256, 256>>>(ei, E, N);
    scan_dinv_kernel<<<1, 1024>>>(N);
    fill_kernel<<<(E + N + 255) / 256, 256>>>(ei, E, N);

    dim3 ggrid((N + 63) / 64, CDIM / 128);   // (157, 4)

    // layer 1: aggregate x (256 cols) -> buf1 ; gemm K=256 (+b1, relu) -> buf0
    spmm_agg<<<N, 64>>>(x, -1, 1, 64);
    gemm_tc<<<ggrid, 128>>>(wr_host[0], b1, nullptr, N, Cin, 1, 0, 1);
    // layer 2
    spmm_agg<<<N, 128>>>(nullptr, 0, 1, 128);
    gemm_tc<<<ggrid, 128>>>(wr_host[1], b2, nullptr, N, CDIM, 1, 0, 1);
    // layer 3
    spmm_agg<<<N, 128>>>(nullptr, 0, 1, 128);
    gemm_tc<<<ggrid, 128>>>(wr_host[2], b3, nullptr, N, CDIM, 1, 0, 1);
    // layer 4 (no relu, write d_out)
    spmm_agg<<<N, 128>>>(nullptr, 0, 1, 128);
    gemm_tc<<<ggrid, 128>>>(wr_host[3], b4, out, N, CDIM, 1, -1, 0);
}

// round 8
// speedup vs baseline: 1.6414x; 1.3180x over previous
#include <cuda_runtime.h>
#include <cuda_fp16.h>
#include <cstdint>

// ---------------------------------------------------------------------------
// GCN, 4 layers:  h_out = relu( (A @ h) @ W + b )   (SpMM first, then GEMM)
// FP16 datapath (same 10-bit mantissa as the previous tf32 pipeline):
//   - h buffers stored fp16; SpMM gathers fp16, accumulates fp32, writes fp16
//   - GEMM mma.sync m16n8k16 f16 -> f32 accum; A frags via ldmatrix.x4;
//     W pre-rounded fp16 AND pre-permuted to fragment order (LDS.128 B loads)
//   - multi-block chunked scan replaces the single-block scan
// edge_index arrives as int32 [2, E] (harness downcasts int64).
// ---------------------------------------------------------------------------

#define NMAX     10016
#define EMAX     200032
#define CDIM     512

__device__ __half g_hbuf[2][NMAX * CDIM];  // fp16 ping-pong feature buffers
__device__ __half g_wh[4][CDIM * CDIM];    // fp16, fragment-permuted weights
__device__ int    g_src[EMAX];
__device__ float  g_w[EMAX];
__device__ int    g_ptr[NMAX + 1];
__device__ int    g_deg[NMAX];
__device__ int    g_cur[NMAX];
__device__ float  g_dinv[NMAX];
__device__ int    g_csum[64];
__device__ int    g_coff[64];

__device__ __forceinline__ int clampi(int v, int n) {
    return v < 0 ? 0 : (v >= n ? n - 1 : v);
}

__device__ __forceinline__ uint32_t smem_u32(const void* p) {
    uint32_t a;
    asm("{ .reg .u64 t; cvta.to.shared.u64 t, %1; cvt.u32.u64 %0, t; }"
        : "=r"(a) : "l"(p));
    return a;
}

#define CP_ASYNC16(dst, src) \
    asm volatile("cp.async.cg.shared.global [%0], [%1], 16;" \
                 :: "r"(dst), "l"(src) : "memory")
#define CP_COMMIT()  asm volatile("cp.async.commit_group;" ::: "memory")
#define CP_WAIT1()   asm volatile("cp.async.wait_group 1;" ::: "memory")
#define CP_WAIT0()   asm volatile("cp.async.wait_group 0;" ::: "memory")

#define LDMATRIX_X4(r0, r1, r2, r3, addr) \
    asm volatile("ldmatrix.sync.aligned.m8n8.x4.shared.b16 {%0,%1,%2,%3}, [%4];" \
                 : "=r"(r0), "=r"(r1), "=r"(r2), "=r"(r3) : "r"(addr))

#define LDS128U(r0, r1, r2, r3, addr) \
    asm volatile("ld.shared.v4.u32 {%0,%1,%2,%3}, [%4];" \
                 : "=r"(r0), "=r"(r1), "=r"(r2), "=r"(r3) : "r"(addr))

// ---------------------------- preprocessing --------------------------------

__global__ void init_kernel(int n) {
    int i = blockIdx.x * blockDim.x + threadIdx.x;
    if (i < n) { g_deg[i] = 1; g_cur[i] = 0; }
}

__global__ void count_kernel(const int* __restrict__ ei, int E, int n) {
    int e = blockIdx.x * blockDim.x + threadIdx.x;
    if (e < E) atomicAdd(&g_deg[clampi(ei[E + e], n)], 1);
}

// chunked scan: pass 1 — per-block sums + dinv
__global__ void chunk_kernel(int n) {
    __shared__ int wsum[16];
    int b = blockIdx.x, t = threadIdx.x;
    int i = b * 512 + t;
    int d = (i < n) ? g_deg[i] : 0;
    if (i < n) g_dinv[i] = rsqrtf((float)d);
    int s = d;
    #pragma unroll
    for (int off = 16; off > 0; off >>= 1)
        s += __shfl_down_sync(0xffffffffu, s, off);
    if ((t & 31) == 0) wsum[t >> 5] = s;
    __syncthreads();
    if (t == 0) {
        int tot = 0;
        #pragma unroll
        for (int w = 0; w < 16; w++) tot += wsum[w];
        g_csum[b] = tot;
    }
}

// pass 2 — exclusive scan of chunk sums (1 warp)
__global__ void scan_chunks(int nc) {
    int t = threadIdx.x;
    int v = (t < nc) ? g_csum[t] : 0;
    int x = v;
    #pragma unroll
    for (int off = 1; off < 32; off <<= 1) {
        int y = __shfl_up_sync(0xffffffffu, x, off);
        if (t >= off) x += y;
    }
    g_coff[t] = x - v;
}

// pass 3 — per-block exclusive scan + chunk offset -> g_ptr
__global__ void apply_kernel(int n) {
    __shared__ int wexc[16];
    int b = blockIdx.x, t = threadIdx.x;
    int i = b * 512 + t;
    int d = (i < n) ? g_deg[i] : 0;
    int lane = t & 31, w = t >> 5;
    int x = d;
    #pragma unroll
    for (int off = 1; off < 32; off <<= 1) {
        int y = __shfl_up_sync(0xffffffffu, x, off);
        if (lane >= off) x += y;
    }
    if (lane == 31) wexc[w] = x;
    __syncthreads();
    if (w == 0 && lane < 16) {
        int v = wexc[lane];
        int z = v;
        #pragma unroll
        for (int off = 1; off < 16; off <<= 1) {
            int y = __shfl_up_sync(0x0000ffffu, z, off);
            if (lane >= off) z += y;
        }
        wexc[lane] = z - v;
    }
    __syncthreads();
    int excl = g_coff[b] + wexc[w] + x - d;
    if (i < n) g_ptr[i] = excl;
    if (i == n - 1) g_ptr[n] = excl + d;
}

__global__ void fill_kernel(const int* __restrict__ ei, int E, int n) {
    int e = blockIdx.x * blockDim.x + threadIdx.x;
    if (e >= E + n) return;
    int r, c;
    if (e < E) { r = clampi(ei[e], n); c = clampi(ei[E + e], n); }
    else       { r = c = e - E; }
    int pos = g_ptr[c] + atomicAdd(&g_cur[c], 1);
    if (pos < EMAX) {
        g_src[pos] = r;
        g_w[pos]   = g_dinv[r] * g_dinv[c];
    }
}

// convert x to fp16 into hbuf0
__global__ void xhalf_kernel(const float* __restrict__ x, int total) {
    int i = blockIdx.x * blockDim.x + threadIdx.x;
    if (i < total) g_hbuf[0][i] = __float2half(x[i]);
}

// ---- weight preprocessing: fp16 round + m16n8k16 fragment permutation -----
// Linear dst index o (halves):
//   h(3b) | lane(5b) | c(2b) | wn2(1b) | kk2(1b) | kt(ktbits) | nb(2b)
//   tg=lane&3, gp=lane>>2, nt=c*2+(h>>2), hw=h&3
//   k = kt*32 + kk2*16 + (hw>>1)*8 + tg*2 + (hw&1)
//   n = nb*128 + wn2*64 + nt*8 + gp
// GEMM lane LDS.128 then yields regs: r0=b0(nt=2c), r1=b1(nt=2c),
// r2=b0(nt=2c+1), r3=b1(nt=2c+1) with b0 = B[k16+tg*2,+1], b1 = B[k16+8+...]
__device__ __forceinline__ void permWh(__half* dst, const float* __restrict__ W,
                                       int o, int ktbits) {
    int h    = o & 7;
    int lane = (o >> 3) & 31;
    int c    = (o >> 8) & 3;
    int wn2  = (o >> 10) & 1;
    int kk2  = (o >> 11) & 1;
    int rest = o >> 12;
    int kt   = rest & ((1 << ktbits) - 1);
    int nb   = rest >> ktbits;
    int tg = lane & 3, gp = lane >> 2;
    int nt = c * 2 + (h >> 2), hw = h & 3;
    int k  = kt * 32 + kk2 * 16 + (hw >> 1) * 8 + tg * 2 + (hw & 1);
    int n  = nb * 128 + wn2 * 64 + nt * 8 + gp;
    dst[o] = __float2half(W[k * CDIM + n]);
}

__global__ void wround_kernel(const float* __restrict__ W1,
                              const float* __restrict__ W2,
                              const float* __restrict__ W3,
                              const float* __restrict__ W4, int n1) {
    int o = blockIdx.x * blockDim.x + threadIdx.x;
    if (o < CDIM * CDIM) {
        permWh(g_wh[1], W2, o, 4);
        permWh(g_wh[2], W3, o, 4);
        permWh(g_wh[3], W4, o, 4);
        if (o < n1) permWh(g_wh[0], W1, o, 3);   // K=256 -> KT=8
    }
}

// ------------------------------- CSR SpMM ----------------------------------
// fp16 gather, fp32 accum, fp16 write. blockDim = cols/8. src/dst fp16 bufs.
__global__ void spmm_h(int srcsel, int dstsel, int c8)
{
    int v = blockIdx.x;
    int t = threadIdx.x;
    const uint4* S = (const uint4*)g_hbuf[srcsel];
    uint4* D = (uint4*)g_hbuf[dstsel];

    int beg = g_ptr[v], end = g_ptr[v + 1];
    float f[8];
    #pragma unroll
    for (int j = 0; j < 8; j++) f[j] = 0.f;

    int e = beg;
    for (; e + 1 < end; e += 2) {
        int   s0 = g_src[e],   s1 = g_src[e + 1];
        float w0 = g_w[e],     w1 = g_w[e + 1];
        uint4 u0 = S[s0 * c8 + t];
        uint4 u1 = S[s1 * c8 + t];
        const half2* p0 = (const half2*)&u0;
        const half2* p1 = (const half2*)&u1;
        #pragma unroll
        for (int q = 0; q < 4; q++) {
            float2 a = __half22float2(p0[q]);
            float2 b = __half22float2(p1[q]);
            f[q * 2 + 0] += w0 * a.x + w1 * b.x;
            f[q * 2 + 1] += w0 * a.y + w1 * b.y;
        }
    }
    if (e < end) {
        int s0 = g_src[e];
        float w0 = g_w[e];
        uint4 u0 = S[s0 * c8 + t];
        const half2* p0 = (const half2*)&u0;
        #pragma unroll
        for (int q = 0; q < 4; q++) {
            float2 a = __half22float2(p0[q]);
            f[q * 2 + 0] += w0 * a.x;
            f[q * 2 + 1] += w0 * a.y;
        }
    }

    uint4 o;
    half2* op = (half2*)&o;
    #pragma unroll
    for (int q = 0; q < 4; q++)
        op[q] = __floats2half2_rn(f[q * 2], f[q * 2 + 1]);
    D[v * c8 + t] = o;
}

// --------------------------- fp16 GEMM (mma.sync) --------------------------
// C[M x 512] = A[M x K] @ W[K x 512] (+bias, +relu). A fp16, W fp16 permuted.
// Block 64x128, BK=32, 128 threads (4 warps 2x2), warp tile 32x64.
// 3-stage cp.async. A frags: ldmatrix.x4 (80B row stride, conflict-free).
// B frags: LDS.128 from fragment-ordered smem (contiguous cp.async from gmem).

__device__ __forceinline__ void mma_f16(float* c, const uint32_t* a,
                                        uint32_t b0, uint32_t b1) {
    asm volatile(
        "mma.sync.aligned.m16n8k16.row.col.f32.f16.f16.f32 "
        "{%0,%1,%2,%3}, {%4,%5,%6,%7}, {%8,%9}, {%0,%1,%2,%3};"
        : "+f"(c[0]), "+f"(c[1]), "+f"(c[2]), "+f"(c[3])
        : "r"(a[0]), "r"(a[1]), "r"(a[2]), "r"(a[3]), "r"(b0), "r"(b1));
}

#define AROWH 40   // A smem row stride in halves (80 B)

__global__ __launch_bounds__(128)
void gemm_h(const __half* __restrict__ Wh, const float* __restrict__ bias,
            float* __restrict__ dout, int M, int K, int insel, int outsel,
            int relu)
{
    __shared__ __align__(16) __half Ah[3][64 * AROWH];  // 5120 B / stage
    __shared__ __align__(16) __half Bh[3][4096];        // 8192 B / stage

    const __half* A = g_hbuf[insel];
    __half* C16 = (outsel < 0) ? nullptr : g_hbuf[outsel];

    int tid  = threadIdx.x;
    int bm   = blockIdx.x * 64;
    int nb   = blockIdx.y;
    int bn   = nb * 128;
    int wid  = tid >> 5, lane = tid & 31;
    int wm   = (wid >> 1) * 32;
    int wn   = (wid & 1) * 64;
    int wn2  = wid & 1;
    int tg   = lane & 3, gp = lane >> 2;

    float acc[2][8][4];
    #pragma unroll
    for (int mt = 0; mt < 2; mt++)
        #pragma unroll
        for (int nt = 0; nt < 8; nt++)
            #pragma unroll
            for (int q = 0; q < 4; q++) acc[mt][nt][q] = 0.f;

    // A copy: rows tid>>2 (+32), seg tid&3 (16B = 8 halves)
    int a_row = tid >> 2, a_seg = tid & 3;
    int gr0 = bm + a_row;      if (gr0 >= M) gr0 = M - 1;
    int gr1 = bm + a_row + 32; if (gr1 >= M) gr1 = M - 1;

    uint32_t AhB[3], BhB[3];
    uint32_t sa0[3], sa1[3];
    #pragma unroll
    for (int s = 0; s < 3; s++) {
        AhB[s] = smem_u32(&Ah[s][0]);
        BhB[s] = smem_u32(&Bh[s][0]);
        sa0[s] = AhB[s] + (a_row * AROWH + a_seg * 8) * 2;
        sa1[s] = sa0[s] + 32 * AROWH * 2;
    }

    // ldmatrix lane address parts (per mt): row + 16B column select
    int lrow  = (lane & 7) + ((lane >> 3) & 1) * 8;
    int lcol  = (lane >> 4) & 1;
    uint32_t lmoff[2];
    #pragma unroll
    for (int mt = 0; mt < 2; mt++)
        lmoff[mt] = ((wm + mt * 16 + lrow) * AROWH) * 2 + lcol * 16;

    int ktiles = K >> 5;

    auto prefetch = [&](int kt) {
        int s  = kt % 3;
        const __half* a0p = A + (size_t)gr0 * K + kt * 32 + a_seg * 8;
        const __half* a1p = A + (size_t)gr1 * K + kt * 32 + a_seg * 8;
        CP_ASYNC16(sa0[s], a0p);
        CP_ASYNC16(sa1[s], a1p);
        const __half* src = Wh + (((size_t)(nb * ktiles + kt)) << 12) + (size_t)tid * 8;
        uint32_t bd = BhB[s] + tid * 16;
        #pragma unroll
        for (int i = 0; i < 4; i++)
            CP_ASYNC16(bd + i * 2048, src + i * 1024);
        CP_COMMIT();
    };

    prefetch(0);
    if (ktiles > 1) prefetch(1); else CP_COMMIT();

    for (int kt = 0; kt < ktiles; kt++) {
        if (kt + 1 < ktiles) CP_WAIT1(); else CP_WAIT0();
        __syncthreads();

        int buf = kt % 3;
        #pragma unroll
        for (int kk2 = 0; kk2 < 2; kk2++) {
            uint32_t a[2][4];
            #pragma unroll
            for (int mt = 0; mt < 2; mt++)
                LDMATRIX_X4(a[mt][0], a[mt][1], a[mt][2], a[mt][3],
                            AhB[buf] + lmoff[mt] + kk2 * 32);
            uint32_t b[8][2];
            #pragma unroll
            for (int c = 0; c < 4; c++) {
                uint32_t q0, q1, q2, q3;
                LDS128U(q0, q1, q2, q3,
                        BhB[buf] + ((kk2 * 2 + wn2) * 4 + c) * 512 + lane * 16);
                b[c * 2 + 0][0] = q0; b[c * 2 + 0][1] = q1;
                b[c * 2 + 1][0] = q2; b[c * 2 + 1][1] = q3;
            }
            #pragma unroll
            for (int mt = 0; mt < 2; mt++)
                #pragma unroll
                for (int nt = 0; nt < 8; nt++)
                    mma_f16(acc[mt][nt], a[mt], b[nt][0], b[nt][1]);
        }

        if (kt + 2 < ktiles) prefetch(kt + 2);
    }

    // epilogue: + bias, optional relu; fp16 to g_hbuf or fp32 to dout
    #pragma unroll
    for (int mt = 0; mt < 2; mt++) {
        #pragma unroll
        for (int nt = 0; nt < 8; nt++) {
            int r = bm + wm + mt * 16 + gp;
            int c = bn + wn + nt * 8 + tg * 2;
            float bb0 = __ldg(&bias[c]), bb1 = __ldg(&bias[c + 1]);
            float v0 = acc[mt][nt][0] + bb0, v1 = acc[mt][nt][1] + bb1;
            float v2 = acc[mt][nt][2] + bb0, v3 = acc[mt][nt][3] + bb1;
            if (relu) {
                v0 = fmaxf(v0, 0.f); v1 = fmaxf(v1, 0.f);
                v2 = fmaxf(v2, 0.f); v3 = fmaxf(v3, 0.f);
            }
            if (outsel < 0) {
                if (r < M)     *(float2*)&dout[(size_t)r * CDIM + c]       = make_float2(v0, v1);
                if (r + 8 < M) *(float2*)&dout[(size_t)(r + 8) * CDIM + c] = make_float2(v2, v3);
            } else {
                if (r < M)     *(half2*)&C16[(size_t)r * CDIM + c]       = __floats2half2_rn(v0, v1);
                if (r + 8 < M) *(half2*)&C16[(size_t)(r + 8) * CDIM + c] = __floats2half2_rn(v2, v3);
            }
        }
    }
}

// ------------------------------- driver ------------------------------------

extern "C" void kernel_launch(void* const* d_in, const int* in_sizes, int n_in,
                              void* d_out, int out_size)
{
    const float* x  = (const float*)d_in[0];
    const int*   ei = (const int*)d_in[1];      // int64 downcast to int32
    const float* W1 = (const float*)d_in[2];
    const float* b1 = (const float*)d_in[3];
    const float* W2 = (const float*)d_in[4];
    const float* b2 = (const float*)d_in[5];
    const float* W3 = (const float*)d_in[6];
    const float* b3 = (const float*)d_in[7];
    const float* W4 = (const float*)d_in[8];
    const float* b4 = (const float*)d_in[9];
    float* out = (float*)d_out;

    int Cin = in_sizes[2] / CDIM;         // 256
    int N   = in_sizes[0] / Cin;          // 10000
    int E   = in_sizes[1] / 2;            // 160000
    int nc  = (N + 511) / 512;            // 20 chunks

    static __half* wh_host[4] = {nullptr, nullptr, nullptr, nullptr};
    if (!wh_host[0]) {
        void* p;
        cudaGetSymbolAddress(&p, g_wh);
        for (int l = 0; l < 4; l++)
            wh_host[l] = (__half*)p + (size_t)l * CDIM * CDIM;
    }

    // preprocessing
    wround_kernel<<<(CDIM * CDIM + 255) / 256, 256>>>(W1, W2, W3, W4, Cin * CDIM);
    xhalf_kernel<<<(N * Cin + 255) / 256, 256>>>(x, N * Cin);
    init_kernel<<<(N + 255) / 256, 256>>>(N);
    count_kernel<<<(E + 255) / 256, 256>>>(ei, E, N);
    chunk_kernel<<<nc, 512>>>(N);
    scan_chunks<<<1, 32>>>(nc);
    apply_kernel<<<nc, 512>>>(N);
    fill_kernel<<<(E + N + 255) / 256, 256>>>(ei, E, N);

    dim3 ggrid((N + 63) / 64, CDIM / 128);   // (157, 4)

    // layer 1: aggregate x16 (256 cols) hbuf0 -> hbuf1 ; gemm K=256 -> hbuf0
    spmm_h<<<N, Cin / 8>>>(0, 1, Cin / 8);
    gemm_h<<<ggrid, 128>>>(wh_host[0], b1, nullptr, N, Cin, 1, 0, 1);
    // layer 2
    spmm_h<<<N, CDIM / 8>>>(0, 1, CDIM / 8);
    gemm_h<<<ggrid, 128>>>(wh_host[1], b2, nullptr, N, CDIM, 1, 0, 1);
    // layer 3
    spmm_h<<<N, CDIM / 8>>>(0, 1, CDIM / 8);
    gemm_h<<<ggrid, 128>>>(wh_host[2], b3, nullptr, N, CDIM, 1, 0, 1);
    // layer 4 (no relu, fp32 out)
    spmm_h<<<N, CDIM / 8>>>(0, 1, CDIM / 8);
    gemm_h<<<ggrid, 128>>>(wh_host[3], b4, out, N, CDIM, 1, -1, 0);
}

// round 9
// speedup vs baseline: 1.6495x; 1.0049x over previous
#include <cuda_runtime.h>
#include <cuda_fp16.h>
#include <cstdint>

// ---------------------------------------------------------------------------
// GCN, 4 layers:  h_out = relu( (A @ h) @ W + b )   (SpMM first, then GEMM)
// FP16 datapath; GEMM mma.sync m16n8k16 (ldmatrix A, fragment-permuted W).
// This round: two-stream preproc overlap, packed (src,w) edge list, int4
// count, SpMM unroll-4.
// ---------------------------------------------------------------------------

#define NMAX     10016
#define EMAX     200032
#define CDIM     512

__device__ __half g_hbuf[2][NMAX * CDIM];  // fp16 ping-pong feature buffers
__device__ __half g_wh[4][CDIM * CDIM];    // fp16, fragment-permuted weights
__device__ int2   g_edge[EMAX];            // packed (src, w-bits), dst-sorted
__device__ int    g_ptr[NMAX + 1];
__device__ int    g_deg[NMAX];
__device__ int    g_cur[NMAX];
__device__ float  g_dinv[NMAX];
__device__ int    g_csum[64];
__device__ int    g_coff[64];

__device__ __forceinline__ int clampi(int v, int n) {
    return v < 0 ? 0 : (v >= n ? n - 1 : v);
}

__device__ __forceinline__ uint32_t smem_u32(const void* p) {
    uint32_t a;
    asm("{ .reg .u64 t; cvta.to.shared.u64 t, %1; cvt.u32.u64 %0, t; }"
        : "=r"(a) : "l"(p));
    return a;
}

#define CP_ASYNC16(dst, src) \
    asm volatile("cp.async.cg.shared.global [%0], [%1], 16;" \
                 :: "r"(dst), "l"(src) : "memory")
#define CP_COMMIT()  asm volatile("cp.async.commit_group;" ::: "memory")
#define CP_WAIT1()   asm volatile("cp.async.wait_group 1;" ::: "memory")
#define CP_WAIT0()   asm volatile("cp.async.wait_group 0;" ::: "memory")

#define LDMATRIX_X4(r0, r1, r2, r3, addr) \
    asm volatile("ldmatrix.sync.aligned.m8n8.x4.shared.b16 {%0,%1,%2,%3}, [%4];" \
                 : "=r"(r0), "=r"(r1), "=r"(r2), "=r"(r3) : "r"(addr))

#define LDS128U(r0, r1, r2, r3, addr) \
    asm volatile("ld.shared.v4.u32 {%0,%1,%2,%3}, [%4];" \
                 : "=r"(r0), "=r"(r1), "=r"(r2), "=r"(r3) : "r"(addr))

// ---------------------------- preprocessing --------------------------------

__global__ void init_kernel(int n) {
    int i = blockIdx.x * blockDim.x + threadIdx.x;
    if (i < n) { g_deg[i] = 1; g_cur[i] = 0; }
}

// 4 edges per thread (cols are contiguous at ei+E, 16B-aligned for E%4==0)
__global__ void count_kernel(const int* __restrict__ ei, int E, int n) {
    int i = blockIdx.x * blockDim.x + threadIdx.x;
    int e4 = i * 4;
    if (e4 + 3 < E) {
        int4 c = *(const int4*)&ei[E + e4];
        atomicAdd(&g_deg[clampi(c.x, n)], 1);
        atomicAdd(&g_deg[clampi(c.y, n)], 1);
        atomicAdd(&g_deg[clampi(c.z, n)], 1);
        atomicAdd(&g_deg[clampi(c.w, n)], 1);
    } else {
        for (int e = e4; e < E; e++)
            atomicAdd(&g_deg[clampi(ei[E + e], n)], 1);
    }
}

// chunked scan: pass 1 — per-block sums + dinv
__global__ void chunk_kernel(int n) {
    __shared__ int wsum[16];
    int b = blockIdx.x, t = threadIdx.x;
    int i = b * 512 + t;
    int d = (i < n) ? g_deg[i] : 0;
    if (i < n) g_dinv[i] = rsqrtf((float)d);
    int s = d;
    #pragma unroll
    for (int off = 16; off > 0; off >>= 1)
        s += __shfl_down_sync(0xffffffffu, s, off);
    if ((t & 31) == 0) wsum[t >> 5] = s;
    __syncthreads();
    if (t == 0) {
        int tot = 0;
        #pragma unroll
        for (int w = 0; w < 16; w++) tot += wsum[w];
        g_csum[b] = tot;
    }
}

// pass 2 — exclusive scan of chunk sums (1 warp)
__global__ void scan_chunks(int nc) {
    int t = threadIdx.x;
    int v = (t < nc) ? g_csum[t] : 0;
    int x = v;
    #pragma unroll
    for (int off = 1; off < 32; off <<= 1) {
        int y = __shfl_up_sync(0xffffffffu, x, off);
        if (t >= off) x += y;
    }
    g_coff[t] = x - v;
}

// pass 3 — per-block exclusive scan + chunk offset -> g_ptr
__global__ void apply_kernel(int n) {
    __shared__ int wexc[16];
    int b = blockIdx.x, t = threadIdx.x;
    int i = b * 512 + t;
    int d = (i < n) ? g_deg[i] : 0;
    int lane = t & 31, w = t >> 5;
    int x = d;
    #pragma unroll
    for (int off = 1; off < 32; off <<= 1) {
        int y = __shfl_up_sync(0xffffffffu, x, off);
        if (lane >= off) x += y;
    }
    if (lane == 31) wexc[w] = x;
    __syncthreads();
    if (w == 0 && lane < 16) {
        int v = wexc[lane];
        int z = v;
        #pragma unroll
        for (int off = 1; off < 16; off <<= 1) {
            int y = __shfl_up_sync(0x0000ffffu, z, off);
            if (lane >= off) z += y;
        }
        wexc[lane] = z - v;
    }
    __syncthreads();
    int excl = g_coff[b] + wexc[w] + x - d;
    if (i < n) g_ptr[i] = excl;
    if (i == n - 1) g_ptr[n] = excl + d;
}

__global__ void fill_kernel(const int* __restrict__ ei, int E, int n) {
    int e = blockIdx.x * blockDim.x + threadIdx.x;
    if (e >= E + n) return;
    int r, c;
    if (e < E) { r = clampi(ei[e], n); c = clampi(ei[E + e], n); }
    else       { r = c = e - E; }
    int pos = g_ptr[c] + atomicAdd(&g_cur[c], 1);
    if (pos < EMAX)
        g_edge[pos] = make_int2(r, __float_as_int(g_dinv[r] * g_dinv[c]));
}

// convert x to fp16 into hbuf0 (vectorized: 4 floats -> 4 halves per thread)
__global__ void xhalf_kernel(const float* __restrict__ x, int total4) {
    int i = blockIdx.x * blockDim.x + threadIdx.x;
    if (i < total4) {
        float4 v = ((const float4*)x)[i];
        half2* D = (half2*)g_hbuf[0];
        D[i * 2 + 0] = __floats2half2_rn(v.x, v.y);
        D[i * 2 + 1] = __floats2half2_rn(v.z, v.w);
    }
}

// ---- weight preprocessing: fp16 round + m16n8k16 fragment permutation -----
__device__ __forceinline__ void permWh(__half* dst, const float* __restrict__ W,
                                       int o, int ktbits) {
    int h    = o & 7;
    int lane = (o >> 3) & 31;
    int c    = (o >> 8) & 3;
    int wn2  = (o >> 10) & 1;
    int kk2  = (o >> 11) & 1;
    int rest = o >> 12;
    int kt   = rest & ((1 << ktbits) - 1);
    int nb   = rest >> ktbits;
    int tg = lane & 3, gp = lane >> 2;
    int nt = c * 2 + (h >> 2), hw = h & 3;
    int k  = kt * 32 + kk2 * 16 + (hw >> 1) * 8 + tg * 2 + (hw & 1);
    int n  = nb * 128 + wn2 * 64 + nt * 8 + gp;
    dst[o] = __float2half(W[k * CDIM + n]);
}

__global__ void wround_kernel(const float* __restrict__ W1,
                              const float* __restrict__ W2,
                              const float* __restrict__ W3,
                              const float* __restrict__ W4, int n1) {
    int o = blockIdx.x * blockDim.x + threadIdx.x;
    if (o < CDIM * CDIM) {
        permWh(g_wh[1], W2, o, 4);
        permWh(g_wh[2], W3, o, 4);
        permWh(g_wh[3], W4, o, 4);
        if (o < n1) permWh(g_wh[0], W1, o, 3);   // K=256 -> KT=8
    }
}

// ------------------------------- CSR SpMM ----------------------------------
// fp16 gather, fp32 accum, fp16 write; packed edges; unroll 4.
__global__ void spmm_h(int srcsel, int dstsel, int c8)
{
    int v = blockIdx.x;
    int t = threadIdx.x;
    const uint4* S = (const uint4*)g_hbuf[srcsel];
    uint4* D = (uint4*)g_hbuf[dstsel];

    int beg = g_ptr[v], end = g_ptr[v + 1];
    float f[8];
    #pragma unroll
    for (int j = 0; j < 8; j++) f[j] = 0.f;

    int e = beg;
    for (; e + 3 < end; e += 4) {
        int2 e0 = g_edge[e],     e1 = g_edge[e + 1];
        int2 e2 = g_edge[e + 2], e3 = g_edge[e + 3];
        uint4 u0 = S[e0.x * c8 + t];
        uint4 u1 = S[e1.x * c8 + t];
        uint4 u2 = S[e2.x * c8 + t];
        uint4 u3 = S[e3.x * c8 + t];
        float w0 = __int_as_float(e0.y), w1 = __int_as_float(e1.y);
        float w2 = __int_as_float(e2.y), w3 = __int_as_float(e3.y);
        const half2* p0 = (const half2*)&u0;
        const half2* p1 = (const half2*)&u1;
        const half2* p2 = (const half2*)&u2;
        const half2* p3 = (const half2*)&u3;
        #pragma unroll
        for (int q = 0; q < 4; q++) {
            float2 a = __half22float2(p0[q]);
            float2 b = __half22float2(p1[q]);
            float2 cc = __half22float2(p2[q]);
            float2 dd = __half22float2(p3[q]);
            f[q * 2 + 0] += w0 * a.x + w1 * b.x + w2 * cc.x + w3 * dd.x;
            f[q * 2 + 1] += w0 * a.y + w1 * b.y + w2 * cc.y + w3 * dd.y;
        }
    }
    for (; e < end; e++) {
        int2 e0 = g_edge[e];
        float w0 = __int_as_float(e0.y);
        uint4 u0 = S[e0.x * c8 + t];
        const half2* p0 = (const half2*)&u0;
        #pragma unroll
        for (int q = 0; q < 4; q++) {
            float2 a = __half22float2(p0[q]);
            f[q * 2 + 0] += w0 * a.x;
            f[q * 2 + 1] += w0 * a.y;
        }
    }

    uint4 o;
    half2* op = (half2*)&o;
    #pragma unroll
    for (int q = 0; q < 4; q++)
        op[q] = __floats2half2_rn(f[q * 2], f[q * 2 + 1]);
    D[v * c8 + t] = o;
}

// --------------------------- fp16 GEMM (mma.sync) --------------------------

__device__ __forceinline__ void mma_f16(float* c, const uint32_t* a,
                                        uint32_t b0, uint32_t b1) {
    asm volatile(
        "mma.sync.aligned.m16n8k16.row.col.f32.f16.f16.f32 "
        "{%0,%1,%2,%3}, {%4,%5,%6,%7}, {%8,%9}, {%0,%1,%2,%3};"
        : "+f"(c[0]), "+f"(c[1]), "+f"(c[2]), "+f"(c[3])
        : "r"(a[0]), "r"(a[1]), "r"(a[2]), "r"(a[3]), "r"(b0), "r"(b1));
}

#define AROWH 40   // A smem row stride in halves (80 B)

__global__ __launch_bounds__(128)
void gemm_h(const __half* __restrict__ Wh, const float* __restrict__ bias,
            float* __restrict__ dout, int M, int K, int insel, int outsel,
            int relu)
{
    __shared__ __align__(16) __half Ah[3][64 * AROWH];  // 5120 B / stage
    __shared__ __align__(16) __half Bh[3][4096];        // 8192 B / stage

    const __half* A = g_hbuf[insel];
    __half* C16 = (outsel < 0) ? nullptr : g_hbuf[outsel];

    int tid  = threadIdx.x;
    int bm   = blockIdx.x * 64;
    int nb   = blockIdx.y;
    int bn   = nb * 128;
    int wid  = tid >> 5, lane = tid & 31;
    int wm   = (wid >> 1) * 32;
    int wn   = (wid & 1) * 64;
    int wn2  = wid & 1;
    int tg   = lane & 3, gp = lane >> 2;

    float acc[2][8][4];
    #pragma unroll
    for (int mt = 0; mt < 2; mt++)
        #pragma unroll
        for (int nt = 0; nt < 8; nt++)
            #pragma unroll
            for (int q = 0; q < 4; q++) acc[mt][nt][q] = 0.f;

    int a_row = tid >> 2, a_seg = tid & 3;
    int gr0 = bm + a_row;      if (gr0 >= M) gr0 = M - 1;
    int gr1 = bm + a_row + 32; if (gr1 >= M) gr1 = M - 1;

    uint32_t AhB[3], BhB[3];
    uint32_t sa0[3], sa1[3];
    #pragma unroll
    for (int s = 0; s < 3; s++) {
        AhB[s] = smem_u32(&Ah[s][0]);
        BhB[s] = smem_u32(&Bh[s][0]);
        sa0[s] = AhB[s] + (a_row * AROWH + a_seg * 8) * 2;
        sa1[s] = sa0[s] + 32 * AROWH * 2;
    }

    int lrow  = (lane & 7) + ((lane >> 3) & 1) * 8;
    int lcol  = (lane >> 4) & 1;
    uint32_t lmoff[2];
    #pragma unroll
    for (int mt = 0; mt < 2; mt++)
        lmoff[mt] = ((wm + mt * 16 + lrow) * AROWH) * 2 + lcol * 16;

    int ktiles = K >> 5;

    auto prefetch = [&](int kt) {
        int s  = kt % 3;
        const __half* a0p = A + (size_t)gr0 * K + kt * 32 + a_seg * 8;
        const __half* a1p = A + (size_t)gr1 * K + kt * 32 + a_seg * 8;
        CP_ASYNC16(sa0[s], a0p);
        CP_ASYNC16(sa1[s], a1p);
        const __half* src = Wh + (((size_t)(nb * ktiles + kt)) << 12) + (size_t)tid * 8;
        uint32_t bd = BhB[s] + tid * 16;
        #pragma unroll
        for (int i = 0; i < 4; i++)
            CP_ASYNC16(bd + i * 2048, src + i * 1024);
        CP_COMMIT();
    };

    prefetch(0);
    if (ktiles > 1) prefetch(1); else CP_COMMIT();

    for (int kt = 0; kt < ktiles; kt++) {
        if (kt + 1 < ktiles) CP_WAIT1(); else CP_WAIT0();
        __syncthreads();

        int buf = kt % 3;
        #pragma unroll
        for (int kk2 = 0; kk2 < 2; kk2++) {
            uint32_t a[2][4];
            #pragma unroll
            for (int mt = 0; mt < 2; mt++)
                LDMATRIX_X4(a[mt][0], a[mt][1], a[mt][2], a[mt][3],
                            AhB[buf] + lmoff[mt] + kk2 * 32);
            uint32_t b[8][2];
            #pragma unroll
            for (int c = 0; c < 4; c++) {
                uint32_t q0, q1, q2, q3;
                LDS128U(q0, q1, q2, q3,
                        BhB[buf] + ((kk2 * 2 + wn2) * 4 + c) * 512 + lane * 16);
                b[c * 2 + 0][0] = q0; b[c * 2 + 0][1] = q1;
                b[c * 2 + 1][0] = q2; b[c * 2 + 1][1] = q3;
            }
            #pragma unroll
            for (int mt = 0; mt < 2; mt++)
                #pragma unroll
                for (int nt = 0; nt < 8; nt++)
                    mma_f16(acc[mt][nt], a[mt], b[nt][0], b[nt][1]);
        }

        if (kt + 2 < ktiles) prefetch(kt + 2);
    }

    // epilogue: + bias, optional relu; fp16 to g_hbuf or fp32 to dout
    #pragma unroll
    for (int mt = 0; mt < 2; mt++) {
        #pragma unroll
        for (int nt = 0; nt < 8; nt++) {
            int r = bm + wm + mt * 16 + gp;
            int c = bn + wn + nt * 8 + tg * 2;
            float bb0 = __ldg(&bias[c]), bb1 = __ldg(&bias[c + 1]);
            float v0 = acc[mt][nt][0] + bb0, v1 = acc[mt][nt][1] + bb1;
            float v2 = acc[mt][nt][2] + bb0, v3 = acc[mt][nt][3] + bb1;
            if (relu) {
                v0 = fmaxf(v0, 0.f); v1 = fmaxf(v1, 0.f);
                v2 = fmaxf(v2, 0.f); v3 = fmaxf(v3, 0.f);
            }
            if (outsel < 0) {
                if (r < M)     *(float2*)&dout[(size_t)r * CDIM + c]       = make_float2(v0, v1);
                if (r + 8 < M) *(float2*)&dout[(size_t)(r + 8) * CDIM + c] = make_float2(v2, v3);
            } else {
                if (r < M)     *(half2*)&C16[(size_t)r * CDIM + c]       = __floats2half2_rn(v0, v1);
                if (r + 8 < M) *(half2*)&C16[(size_t)(r + 8) * CDIM + c] = __floats2half2_rn(v2, v3);
            }
        }
    }
}

// ------------------------------- driver ------------------------------------

extern "C" void kernel_launch(void* const* d_in, const int* in_sizes, int n_in,
                              void* d_out, int out_size)
{
    const float* x  = (const float*)d_in[0];
    const int*   ei = (const int*)d_in[1];      // int64 downcast to int32
    const float* W1 = (const float*)d_in[2];
    const float* b1 = (const float*)d_in[3];
    const float* W2 = (const float*)d_in[4];
    const float* b2 = (const float*)d_in[5];
    const float* W3 = (const float*)d_in[6];
    const float* b3 = (const float*)d_in[7];
    const float* W4 = (const float*)d_in[8];
    const float* b4 = (const float*)d_in[9];
    float* out = (float*)d_out;

    int Cin = in_sizes[2] / CDIM;         // 256
    int N   = in_sizes[0] / Cin;          // 10000
    int E   = in_sizes[1] / 2;            // 160000
    int nc  = (N + 511) / 512;            // 20 chunks

    static __half* wh_host[4] = {nullptr, nullptr, nullptr, nullptr};
    static cudaStream_t sB = nullptr;
    static cudaEvent_t evFork = nullptr, evJoin = nullptr;
    if (!wh_host[0]) {
        void* p;
        cudaGetSymbolAddress(&p, g_wh);
        for (int l = 0; l < 4; l++)
            wh_host[l] = (__half*)p + (size_t)l * CDIM * CDIM;
        cudaStreamCreateWithFlags(&sB, cudaStreamNonBlocking);
        cudaEventCreateWithFlags(&evFork, cudaEventDisableTiming);
        cudaEventCreateWithFlags(&evJoin, cudaEventDisableTiming);
    }

    // fork: weight/feature conversion on side stream, graph preproc on main
    cudaEventRecord(evFork, 0);
    cudaStreamWaitEvent(sB, evFork, 0);
    wround_kernel<<<(CDIM * CDIM + 255) / 256, 256, 0, sB>>>(W1, W2, W3, W4,
                                                            Cin * CDIM);
    xhalf_kernel<<<(N * Cin / 4 + 255) / 256, 256, 0, sB>>>(x, N * Cin / 4);
    cudaEventRecord(evJoin, sB);

    init_kernel<<<(N + 255) / 256, 256>>>(N);
    count_kernel<<<(E / 4 + 255) / 256, 256>>>(ei, E, N);
    chunk_kernel<<<nc, 512>>>(N);
    scan_chunks<<<1, 32>>>(nc);
    apply_kernel<<<nc, 512>>>(N);
    fill_kernel<<<(E + N + 255) / 256, 256>>>(ei, E, N);
    cudaStreamWaitEvent(0, evJoin, 0);   // join before layers

    dim3 ggrid((N + 63) / 64, CDIM / 128);   // (157, 4)

    // layer 1: aggregate x16 (256 cols) hbuf0 -> hbuf1 ; gemm K=256 -> hbuf0
    spmm_h<<<N, Cin / 8>>>(0, 1, Cin / 8);
    gemm_h<<<ggrid, 128>>>(wh_host[0], b1, nullptr, N, Cin, 1, 0, 1);
    // layer 2
    spmm_h<<<N, CDIM / 8>>>(0, 1, CDIM / 8);
    gemm_h<<<ggrid, 128>>>(wh_host[1], b2, nullptr, N, CDIM, 1, 0, 1);
    // layer 3
    spmm_h<<<N, CDIM / 8>>>(0, 1, CDIM / 8);
    gemm_h<<<ggrid, 128>>>(wh_host[2], b3, nullptr, N, CDIM, 1, 0, 1);
    // layer 4 (no relu, fp32 out)
    spmm_h<<<N, CDIM / 8>>>(0, 1, CDIM / 8);
    gemm_h<<<ggrid, 128>>>(wh_host[3], b4, out, N, CDIM, 1, -1, 0);
}